// round 11
// baseline (speedup 1.0000x reference)
#include <cuda_runtime.h>
#include <math.h>

// Allocation-free scratch.
__device__ float    g_wpart[128];   // per-block partial sum of |W|
__device__ int      g_dot[8192];    // [batch][o] exact integer sign-dots
__device__ unsigned g_count;        // monotone arrival counter (replay-safe)

static __device__ __forceinline__ int sgn(float v) {
    return (v > 0.0f) - (v < 0.0f);
}
static __device__ __forceinline__ int pack_sgn(float4 v) {
    return (sgn(v.x) & 0xFF) | ((sgn(v.y) & 0xFF) << 8)
         | ((sgn(v.z) & 0xFF) << 16) | ((sgn(v.w) & 0xFF) << 24);
}

// Single fused kernel: 128 blocks x 256 threads (one wave).
// Block b owns W rows [8b, 8b+8). Thread t owns columns [4t, 4t+4).
__global__ __launch_bounds__(256, 1)
void k_fused(const float* __restrict__ hidden,   // (8, 4096, 1024)
             const float* __restrict__ W,        // (1024, 1024)
             const float* __restrict__ bias,     // (1024,)
             const float* __restrict__ alpha,    // (1,)
             float* __restrict__ out)            // (8, 1, 1024)
{
    const int t   = threadIdx.x;
    const int blk = blockIdx.x;
    const int o0  = blk * 8;
    const int wid = t >> 5, lid = t & 31;

    __shared__ int      s_p[8][8][4];  // [row][warp][batch-pair] packed int16x2
    __shared__ float    s_a[8];
    __shared__ float    s_r[8];
    __shared__ float    s_ws;
    __shared__ unsigned s_last;

    // Pack x signs once: 8 batches x 4 columns -> 8 int8x4 regs.
    int sx[8];
    #pragma unroll
    for (int bt = 0; bt < 8; bt++) {
        float4 x4 = reinterpret_cast<const float4*>(
            hidden + (size_t)bt * 4096 * 1024)[t];
        sx[bt] = pack_sgn(x4);
    }

    // Preload all 8 W rows (MLP=8 for the DRAM loads).
    float4 w[8];
    #pragma unroll
    for (int r = 0; r < 8; r++)
        w[r] = reinterpret_cast<const float4*>(W + (size_t)(o0 + r) * 1024)[t];

    float asum = 0.0f;
    #pragma unroll
    for (int r = 0; r < 8; r++) {
        const float4 w4 = w[r];
        asum += fabsf(w4.x) + fabsf(w4.y) + fabsf(w4.z) + fabsf(w4.w);
        const int sw = pack_sgn(w4);

        int d[8];
        #pragma unroll
        for (int bt = 0; bt < 8; bt++) d[bt] = __dp4a(sw, sx[bt], 0);

        // Pack batch pairs into int16x2 (|partial| <= 1024, fits s16).
        int p[4];
        #pragma unroll
        for (int j = 0; j < 4; j++)
            p[j] = (d[2 * j] & 0xFFFF) | (d[2 * j + 1] << 16);

        #pragma unroll
        for (int off = 16; off > 0; off >>= 1) {
            #pragma unroll
            for (int j = 0; j < 4; j++)
                p[j] = __vadd2(p[j], __shfl_down_sync(0xFFFFFFFFu, p[j], off));
        }
        if (lid == 0) {
            #pragma unroll
            for (int j = 0; j < 4; j++) s_p[r][wid][j] = p[j];
        }
    }

    // One |W| reduction for the whole block (only the global mean is needed).
    #pragma unroll
    for (int off = 16; off > 0; off >>= 1)
        asum += __shfl_down_sync(0xFFFFFFFFu, asum, off);
    if (lid == 0) s_a[wid] = asum;
    __syncthreads();

    // Finish cross-warp sums; write scratch.
    if (t < 32) {                     // 32 (row, pair) combos
        const int r = t >> 2, j = t & 3;
        int s = s_p[r][0][j];
        #pragma unroll
        for (int wq = 1; wq < 8; wq++) s = __vadd2(s, s_p[r][wq][j]);
        const int lo = (int)(short)(s & 0xFFFF);
        const int hi = (int)(s >> 16);         // arithmetic shift: sign-extended
        const int o  = o0 + r;
        g_dot[(2 * j)     * 1024 + o] = lo;
        g_dot[(2 * j + 1) * 1024 + o] = hi;
    } else if (t == 64) {
        float a2 = 0.0f;
        #pragma unroll
        for (int wq = 0; wq < 8; wq++) a2 += s_a[wq];
        g_wpart[blk] = a2;
    }

    // Publish, then elect the last-arriving block (replay-safe: mask, no reset).
    __threadfence();
    __syncthreads();
    if (t == 0) {
        const unsigned old = atomicAdd(&g_count, 1u);
        s_last = ((old & 127u) == 127u) ? 1u : 0u;
    }
    __syncthreads();
    if (!s_last) return;

    __threadfence();  // acquire side

    // Deterministic fixed-order sum of the 128 block partials.
    float p = (t < 128) ? g_wpart[t] : 0.0f;
    #pragma unroll
    for (int off = 16; off > 0; off >>= 1)
        p += __shfl_down_sync(0xFFFFFFFFu, p, off);
    if (lid == 0) s_r[wid] = p;
    __syncthreads();
    if (t == 0)
        s_ws = (s_r[0] + s_r[1] + s_r[2] + s_r[3]) * (1.0f / (1024.0f * 1024.0f));
    __syncthreads();

    const float a     = fmaxf(alpha[0], 1e-5f);
    const float scale = a * s_ws;
    for (int i = t; i < 8192; i += 256)
        out[i] = tanhf(scale * (float)g_dot[i] + bias[i & 1023]);
}

extern "C" void kernel_launch(void* const* d_in, const int* in_sizes, int n_in,
                              void* d_out, int out_size) {
    const float* hidden = (const float*)d_in[0];
    const float* W      = (const float*)d_in[1];
    const float* bias   = (const float*)d_in[2];
    const float* alpha  = (const float*)d_in[3];
    float* out = (float*)d_out;

    k_fused<<<128, 256>>>(hidden, W, bias, alpha, out);
}